// round 17
// baseline (speedup 1.0000x reference)
#include <cuda_runtime.h>

typedef unsigned long long u64;

#define BATCH 32
#define NSEQ  2048
#define F     32
#define SPLITS1 64              // k1 splits (32 rows each)
#define ROWS1 32
#define INV_N (1.0f / 2048.0f)

// Scratch (fully overwritten every launch -> deterministic)
__device__ float g_Spart[BATCH * SPLITS1 * F * F];  // xT @ u partials
__device__ float g_supart[BATCH * SPLITS1 * F];     // colsum(u) partials
__device__ float g_uwT[BATCH * F * NSEQ];           // (u @ w_r) transposed
__device__ float g_M3[BATCH * F * F];               // W_psi @ (M @ w_r * invN)
__device__ float g_b3[BATCH * F];                   // b_psi @ (M @ w_r * invN)
__device__ float g_G[F * F];                        // W_psi @ W_phi^T
__device__ float g_v[F];                            // W_psi@b_phi + W_phi@b_psi
__device__ float g_c[1];                            // b_psi . b_phi
__device__ unsigned int g_done[BATCH];              // zero-init; self-resetting

// ---- packed f32x2 helpers ----
__device__ __forceinline__ u64 pk2(float a, float b) {
    u64 r; asm("mov.b64 %0,{%1,%2};" : "=l"(r) : "f"(a), "f"(b)); return r;
}
__device__ __forceinline__ float2 up2(u64 v) {
    float2 f; asm("mov.b64 {%0,%1},%2;" : "=f"(f.x), "=f"(f.y) : "l"(v)); return f;
}
__device__ __forceinline__ u64 ffma2(u64 a, u64 b, u64 c) {
    u64 d; asm("fma.rn.f32x2 %0,%1,%2,%3;" : "=l"(d) : "l"(a), "l"(b), "l"(c)); return d;
}
__device__ __forceinline__ u64 add2(u64 a, u64 b) {
    u64 d; asm("add.rn.f32x2 %0,%1,%2;" : "=l"(d) : "l"(a), "l"(b)); return d;
}

// ---------------------------------------------------------------------------
// k1: 32 rows/block, 2048 blocks. warp = 8 rows x 4 feature-quarters.
//   u = relu(x@Wu + bu); uw = u@w_r -> g_uwT; S_part = x^T u; su_part.
// Tail: last block per batch (threadfence counter) reduces S -> M -> M2 ->
//   M3/b3 and writes G/v/c (identical from each reducing block).
// ---------------------------------------------------------------------------
__global__ __launch_bounds__(128) void k1(
    const float* __restrict__ x,
    const float* __restrict__ w_u,   const float* __restrict__ b_u,
    const float* __restrict__ w_r,
    const float* __restrict__ w_phi, const float* __restrict__ b_phi,
    const float* __restrict__ w_psi, const float* __restrict__ b_psi)
{
    __shared__ alignas(16) float ws_u[F * F], ws_r[F * F];
    __shared__ alignas(16) float bs_u[F];
    __shared__ alignas(16) float x36[ROWS1 * 36];   // stride 36: .128-aligned
    __shared__ alignas(16) float u34[ROWS1 * 34];
    __shared__ alignas(16) float sus[F], bfs[F], bps[F];
    __shared__ int s_isLast;

    const int b     = blockIdx.x;
    const int split = blockIdx.y;
    const int t     = threadIdx.x;
    const int w     = t >> 5;
    const int lane  = t & 31;
    const int qq    = lane >> 3;
    const int rr    = lane & 7;
    const int r     = w * 8 + rr;            // local row 0..31
    const int hoff  = qq * 8;

#pragma unroll
    for (int i = t; i < 256; i += 128) {
        ((float4*)ws_u)[i] = ((const float4*)w_u)[i];
        ((float4*)ws_r)[i] = ((const float4*)w_r)[i];
    }
    if (t < F) bs_u[t] = b_u[t];

    const int base = split * ROWS1;
    {   // stage x tile (32x32 -> stride 36, float4 aligned)
        const float* xg = x + ((size_t)b * NSEQ + base) * F;
#pragma unroll
        for (int i = t; i < 256; i += 128) {
            int row = i >> 3, c = (i & 7) << 2;
            float4 v = ((const float4*)xg)[i];
            *(float4*)(x36 + row * 36 + c) = v;
        }
    }
    __syncthreads();

    // ---- u = relu(bu + x@Wu), 8 feats; paired x broadcast loads ----
    u64 uv[4];
#pragma unroll
    for (int i = 0; i < 4; i++) uv[i] = ((const u64*)bs_u)[qq * 4 + i];
#pragma unroll
    for (int k = 0; k < F; k += 2) {
        float2 xf = up2(*(const u64*)(x36 + r * 36 + k));   // aligned: k even
        {
            const u64 xk2 = pk2(xf.x, xf.x);
            const ulonglong2* wu = (const ulonglong2*)(ws_u + k * F + hoff);
            ulonglong2 a0 = wu[0], a1 = wu[1];
            uv[0] = ffma2(xk2, a0.x, uv[0]); uv[1] = ffma2(xk2, a0.y, uv[1]);
            uv[2] = ffma2(xk2, a1.x, uv[2]); uv[3] = ffma2(xk2, a1.y, uv[3]);
        }
        {
            const u64 xk2 = pk2(xf.y, xf.y);
            const ulonglong2* wu = (const ulonglong2*)(ws_u + (k + 1) * F + hoff);
            ulonglong2 a0 = wu[0], a1 = wu[1];
            uv[0] = ffma2(xk2, a0.x, uv[0]); uv[1] = ffma2(xk2, a0.y, uv[1]);
            uv[2] = ffma2(xk2, a1.x, uv[2]); uv[3] = ffma2(xk2, a1.y, uv[3]);
        }
    }
#pragma unroll
    for (int i = 0; i < 4; i++) {
        float2 tu = up2(uv[i]);
        uv[i] = pk2(fmaxf(tu.x, 0.0f), fmaxf(tu.y, 0.0f));
    }
#pragma unroll
    for (int i = 0; i < 4; i++)
        ((u64*)(u34 + r * 34 + hoff))[i] = uv[i];
    __syncthreads();

    // ---- uw = u @ w_r (8 feats), paired u broadcast; persist transposed ----
    const int grow = base + r;
    u64 uw[4] = {0,0,0,0};
#pragma unroll
    for (int f = 0; f < F; f += 2) {
        float2 uf = up2(*(const u64*)(u34 + r * 34 + f));   // aligned: f even
        {
            const u64 uf2 = pk2(uf.x, uf.x);
            const ulonglong2* wr = (const ulonglong2*)(ws_r + f * F + hoff);
            ulonglong2 a0 = wr[0], a1 = wr[1];
            uw[0] = ffma2(uf2, a0.x, uw[0]); uw[1] = ffma2(uf2, a0.y, uw[1]);
            uw[2] = ffma2(uf2, a1.x, uw[2]); uw[3] = ffma2(uf2, a1.y, uw[3]);
        }
        {
            const u64 uf2 = pk2(uf.y, uf.y);
            const ulonglong2* wr = (const ulonglong2*)(ws_r + (f + 1) * F + hoff);
            ulonglong2 a0 = wr[0], a1 = wr[1];
            uw[0] = ffma2(uf2, a0.x, uw[0]); uw[1] = ffma2(uf2, a0.y, uw[1]);
            uw[2] = ffma2(uf2, a1.x, uw[2]); uw[3] = ffma2(uf2, a1.y, uw[3]);
        }
    }
#pragma unroll
    for (int i = 0; i < 4; i++) {
        float2 v = up2(uw[i]);
        g_uwT[((size_t)b * F + hoff + 2*i + 0) * NSEQ + grow] = v.x;
        g_uwT[((size_t)b * F + hoff + 2*i + 1) * NSEQ + grow] = v.y;
    }

    // ---- S_part[k][f2] = sum_j x[j][k]*u[j][f2]; su_part = colsum(u) ----
    u64 acc2[4] = {0,0,0,0};
    float susum = 0.0f;
#pragma unroll 4
    for (int j = 0; j < ROWS1; j++) {
        const float uj = u34[j * 34 + lane];
        const u64 uj2 = pk2(uj, uj);
        const ulonglong2* xr2 = (const ulonglong2*)(x36 + j * 36 + w * 8);
        ulonglong2 p0 = xr2[0], p1 = xr2[1];
        acc2[0] = ffma2(uj2, p0.x, acc2[0]);
        acc2[1] = ffma2(uj2, p0.y, acc2[1]);
        acc2[2] = ffma2(uj2, p1.x, acc2[2]);
        acc2[3] = ffma2(uj2, p1.y, acc2[3]);
        susum += uj;
    }
    float* sp = g_Spart + ((size_t)(b * SPLITS1 + split)) * F * F;
#pragma unroll
    for (int q = 0; q < 4; q++) {
        float2 v = up2(acc2[q]);
        sp[(8*w + 2*q + 0) * F + lane] = v.x;
        sp[(8*w + 2*q + 1) * F + lane] = v.y;
    }
    if (w == 0)
        g_supart[(b * SPLITS1 + split) * F + lane] = susum;

    // ======== tail: last block of this batch performs the reduction ========
    __threadfence();            // publish S/su/uwT stores (all threads)
    __syncthreads();
    if (t == 0) {
        unsigned int n = atomicAdd(&g_done[b], 1u);
        s_isLast = (n == SPLITS1 - 1) ? 1 : 0;
    }
    __syncthreads();
    if (!s_isLast) return;
    __threadfence();            // acquire: observe all other blocks' stores
    if (t == 0) g_done[b] = 0;  // reset for next launch/replay

    // smem aliases for the reduce phase (prior contents dead)
    float* Ss  = u34;           // 1024 <= 1088
    float* wfs = ws_u;          // w_phi
    float* wps = x36;           // w_psi (1024 <= 1152)
    float* wrs = ws_r;          // still holds w_r

#pragma unroll
    for (int i = t; i < 256; i += 128) {
        ((float4*)wfs)[i] = ((const float4*)w_phi)[i];
        ((float4*)wps)[i] = ((const float4*)w_psi)[i];
    }
    for (int e = t; e < F * F; e += 128) {
        float s = 0.0f;
        const float* spp = g_Spart + (size_t)b * SPLITS1 * F * F + e;
#pragma unroll 8
        for (int q = 0; q < SPLITS1; q++) s += spp[q * F * F];
        Ss[e] = s;
    }
    if (t < F) {
        float s = 0.0f;
        const float* up = g_supart + (size_t)b * SPLITS1 * F + t;
#pragma unroll 8
        for (int q = 0; q < SPLITS1; q++) s += up[q * F];
        sus[t] = s;
        bfs[t] = b_phi[t];
        bps[t] = b_psi[t];
    }
    __syncthreads();

    const int f1 = t >> 2;            // 0..31
    const int c0 = (t & 3) * 8;       // 0,8,16,24

    // G = Wpsi @ Wphi^T (identical from all 32 reducing blocks)
    {
        float g[8] = {0,0,0,0,0,0,0,0};
        for (int f = 0; f < F; f++) {
            const float pw = wps[f1 * F + f];
#pragma unroll
            for (int j = 0; j < 8; j++) g[j] += pw * wfs[(c0 + j) * F + f];
        }
#pragma unroll
        for (int j = 0; j < 8; j++) g_G[f1 * F + c0 + j] = g[j];
    }
    if (t < F) {
        float s = 0.f;
        for (int f = 0; f < F; f++)
            s += wps[t * F + f] * bfs[f] + wfs[t * F + f] * bps[f];
        g_v[t] = s;
    }
    if (t == 0) {
        float s = 0.f;
        for (int f = 0; f < F; f++) s += bps[f] * bfs[f];
        g_c[0] = s;
    }

    // M[f1][c] = sum_m Wphi[m][f1]*S[m][c] + bphi[f1]*su[c]
    float mreg[8];
    {
        const float bf = bfs[f1];
#pragma unroll
        for (int j = 0; j < 8; j++) mreg[j] = bf * sus[c0 + j];
        for (int m = 0; m < F; m++) {
            const float wv = wfs[m * F + f1];
#pragma unroll
            for (int j = 0; j < 8; j++) mreg[j] += wv * Ss[m * F + c0 + j];
        }
    }
    __syncthreads();                    // all Ss reads complete
#pragma unroll
    for (int j = 0; j < 8; j++) Ss[f1 * F + c0 + j] = mreg[j];   // Ss := M
    __syncthreads();

    // M2 = M @ wr * invN
    {
        float m2[8] = {0,0,0,0,0,0,0,0};
        for (int m = 0; m < F; m++) {
            const float mv = Ss[f1 * F + m];
#pragma unroll
            for (int j = 0; j < 8; j++) m2[j] += mv * wrs[m * F + c0 + j];
        }
        __syncthreads();                // all M reads complete
#pragma unroll
        for (int j = 0; j < 8; j++) Ss[f1 * F + c0 + j] = m2[j] * INV_N; // Ss := M2
    }
    __syncthreads();

    // M3 = Wpsi @ M2 ; b3 = bpsi @ M2
    {
        float m3[8] = {0,0,0,0,0,0,0,0};
        for (int m = 0; m < F; m++) {
            const float wv = wps[f1 * F + m];
#pragma unroll
            for (int j = 0; j < 8; j++) m3[j] += wv * Ss[m * F + c0 + j];
        }
#pragma unroll
        for (int j = 0; j < 8; j++)
            g_M3[(size_t)b * F * F + f1 * F + c0 + j] = m3[j];
    }
    if (t < 8) {
        const int f = t * 4;
        float a0 = 0.f, a1 = 0.f, a2 = 0.f, a3 = 0.f;
        for (int m = 0; m < F; m++) {
            const float bv = bps[m];
            a0 += bv * Ss[m * F + f + 0];
            a1 += bv * Ss[m * F + f + 1];
            a2 += bv * Ss[m * F + f + 2];
            a3 += bv * Ss[m * F + f + 3];
        }
        *(float4*)(g_b3 + (size_t)b * F + f) = make_float4(a0, a1, a2, a3);
    }
}

// ---------------------------------------------------------------------------
// k_main: 4 thr/row, 32 rows/block, 2048 blocks; paired x broadcast loads.
//   out = x + x@M3 + b3 - ((x@G.x + x.v + c)/N) * uw
// ---------------------------------------------------------------------------
__global__ __launch_bounds__(128) void k_main(
    const float* __restrict__ x, float* __restrict__ out)
{
    __shared__ alignas(16) float Gs[F * F], m3s[F * F];
    __shared__ alignas(16) float vs[F], b3s[F];
    __shared__ alignas(16) float x34[32 * 34];
    __shared__ float cs1;

    const int b     = blockIdx.x >> 6;
    const int chunk = blockIdx.x & 63;
    const int t     = threadIdx.x;
    const int w     = t >> 5;
    const int lane  = t & 31;
    const int qq    = lane >> 3;
    const int rr    = lane & 7;
    const int r     = w * 8 + rr;
    const int hoff  = qq * 8;

#pragma unroll
    for (int i = t; i < 256; i += 128) {
        ((float4*)Gs )[i] = ((const float4*)g_G)[i];
        ((float4*)m3s)[i] = ((const float4*)(g_M3 + (size_t)b * F * F))[i];
    }
    if (t < F) { vs[t] = g_v[t]; b3s[t] = g_b3[(size_t)b * F + t]; }
    if (t == 0) cs1 = g_c[0];

    const int base = chunk * 32;
    {
        const float* xg = x + ((size_t)b * NSEQ + base) * F;
#pragma unroll
        for (int i = t; i < 256; i += 128) {
            int row = i >> 3, c = (i & 7) << 2;
            float4 v = ((const float4*)xg)[i];
            float* dst = x34 + row * 34 + c;     // scalar stores (alignment-safe)
            dst[0] = v.x; dst[1] = v.y; dst[2] = v.z; dst[3] = v.w;
        }
    }

    const int myrow = base + r;
    float uwv[8];
    {
        const float* uwb = g_uwT + ((size_t)b * F + hoff) * NSEQ + myrow;
#pragma unroll
        for (int i = 0; i < 8; i++) uwv[i] = uwb[(size_t)i * NSEQ];
    }
    __syncthreads();

    u64 xp[4];
#pragma unroll
    for (int i = 0; i < 4; i++) xp[i] = ((const u64*)(x34 + r * 34 + hoff))[i];

    u64 o[4], tt[4];
#pragma unroll
    for (int i = 0; i < 4; i++) { o[i] = ((const u64*)b3s)[qq * 4 + i]; tt[i] = 0ull; }
#pragma unroll
    for (int k = 0; k < F; k += 2) {
        float2 xf = up2(*(const u64*)(x34 + r * 34 + k));   // aligned: k even
        {
            const u64 xk2 = pk2(xf.x, xf.x);
            const ulonglong2* mr = (const ulonglong2*)(m3s + k * F + hoff);
            const ulonglong2* gr = (const ulonglong2*)(Gs  + k * F + hoff);
            ulonglong2 a0 = mr[0], a1 = mr[1];
            o[0] = ffma2(xk2, a0.x, o[0]); o[1] = ffma2(xk2, a0.y, o[1]);
            o[2] = ffma2(xk2, a1.x, o[2]); o[3] = ffma2(xk2, a1.y, o[3]);
            ulonglong2 g0 = gr[0], g1 = gr[1];
            tt[0] = ffma2(xk2, g0.x, tt[0]); tt[1] = ffma2(xk2, g0.y, tt[1]);
            tt[2] = ffma2(xk2, g1.x, tt[2]); tt[3] = ffma2(xk2, g1.y, tt[3]);
        }
        {
            const u64 xk2 = pk2(xf.y, xf.y);
            const ulonglong2* mr = (const ulonglong2*)(m3s + (k + 1) * F + hoff);
            const ulonglong2* gr = (const ulonglong2*)(Gs  + (k + 1) * F + hoff);
            ulonglong2 a0 = mr[0], a1 = mr[1];
            o[0] = ffma2(xk2, a0.x, o[0]); o[1] = ffma2(xk2, a0.y, o[1]);
            o[2] = ffma2(xk2, a1.x, o[2]); o[3] = ffma2(xk2, a1.y, o[3]);
            ulonglong2 g0 = gr[0], g1 = gr[1];
            tt[0] = ffma2(xk2, g0.x, tt[0]); tt[1] = ffma2(xk2, g0.y, tt[1]);
            tt[2] = ffma2(xk2, g1.x, tt[2]); tt[3] = ffma2(xk2, g1.y, tt[3]);
        }
    }

    u64 dacc = 0ull;
#pragma unroll
    for (int i = 0; i < 4; i++) {
        u64 tv = add2(tt[i], ((const u64*)vs)[qq * 4 + i]);
        dacc = ffma2(tv, xp[i], dacc);
    }
    float2 dd = up2(dacc);
    float d = dd.x + dd.y;
    d += __shfl_xor_sync(0xffffffffu, d, 8);
    d += __shfl_xor_sync(0xffffffffu, d, 16);
    const float s = (d + cs1) * INV_N;
    const u64 ns2 = pk2(-s, -s);

#pragma unroll
    for (int i = 0; i < 4; i++) {
        o[i] = add2(o[i], xp[i]);
        o[i] = ffma2(ns2, pk2(uwv[2*i + 0], uwv[2*i + 1]), o[i]);
    }

    float* op = out + ((size_t)b * NSEQ + myrow) * F + hoff;
#pragma unroll
    for (int q = 0; q < 2; q++) {
        float2 lo = up2(o[2*q+0]), hi = up2(o[2*q+1]);
        ((float4*)op)[q] = make_float4(lo.x, lo.y, hi.x, hi.y);
    }
}

// ---------------------------------------------------------------------------
extern "C" void kernel_launch(void* const* d_in, const int* in_sizes, int n_in,
                              void* d_out, int out_size)
{
    const float* x     = (const float*)d_in[0];
    const float* w_psi = (const float*)d_in[1];
    const float* b_psi = (const float*)d_in[2];
    const float* w_phi = (const float*)d_in[3];
    const float* b_phi = (const float*)d_in[4];
    const float* w_u   = (const float*)d_in[5];
    const float* b_u   = (const float*)d_in[6];
    const float* w_r   = (const float*)d_in[7];
    float* out = (float*)d_out;

    dim3 g1(BATCH, SPLITS1);
    k1<<<g1, 128>>>(x, w_u, b_u, w_r, w_phi, b_phi, w_psi, b_psi);
    k_main<<<BATCH * 64, 128>>>(x, out);
}